// round 11
// baseline (speedup 1.0000x reference)
#include <cuda_runtime.h>
#include <cuda_fp16.h>
#include <cstdint>

// DistMult edge score: out[e] = sum_d node[src[e]][d] * rel[e][d] * node[dst[e]][d]
// N_NODES=100000, N_EDGES=600000, DIM=128, int32 indices.
//
// R10 (61.9us): fp16 node-table scratch broke the LTS cap (DRAM 66->78%).
// R11: L2 policy plumbing to kill the ~25MB cold-miss term:
//  - convert: read fp32 table evict_first (read-once), write fp16 table
//    evict_last (pin 25.6MB in L2 across the kernel boundary)
//  - score:   gather node16 rows evict_last, rel stream stays __ldcs
// Main kernel shape unchanged from R10 (EPW=4, 32 regs, occ 86%).

#define DIM       128
#define DIM4      32            // 16B groups per row
#define EPW       4             // edges per warp
#define MAX_NODES 100000

__device__ __half g_node16[(size_t)MAX_NODES * DIM];   // 25.6 MB scratch

// ---- Kernel 1: fp32 node table -> fp16 scratch ----
__global__ __launch_bounds__(256)
void convert_kernel(const float* __restrict__ node_emb, int total4) {
    int i = blockIdx.x * blockDim.x + threadIdx.x;
    if (i >= total4) return;

    uint64_t pol_first, pol_last;
    asm("createpolicy.fractional.L2::evict_first.b64 %0, 1.0;" : "=l"(pol_first));
    asm("createpolicy.fractional.L2::evict_last.b64 %0, 1.0;"  : "=l"(pol_last));

    // read-once fp32 row chunk, evict_first
    float4 v;
    asm volatile("ld.global.L2::cache_hint.v4.f32 {%0,%1,%2,%3}, [%4], %5;"
                 : "=f"(v.x), "=f"(v.y), "=f"(v.z), "=f"(v.w)
                 : "l"(reinterpret_cast<const float4*>(node_emb) + i),
                   "l"(pol_first));

    __half2 a = __floats2half2_rn(v.x, v.y);
    __half2 b = __floats2half2_rn(v.z, v.w);
    unsigned int lo = *reinterpret_cast<unsigned int*>(&a);
    unsigned int hi = *reinterpret_cast<unsigned int*>(&b);

    // fp16 table write, evict_last: keep resident for the scorer's gathers
    asm volatile("st.global.L2::cache_hint.v2.u32 [%0], {%1,%2}, %3;"
                 :: "l"(reinterpret_cast<uint2*>(g_node16) + i),
                    "r"(lo), "r"(hi), "l"(pol_last)
                 : "memory");
}

// ---- Kernel 2: R10-shape scorer reading fp16 node rows ----
__global__ __launch_bounds__(256)
void distmult_kernel(const float* __restrict__ rel_emb,
                     const int* __restrict__ src,
                     const int* __restrict__ dst,
                     float* __restrict__ out,
                     int n_edges,
                     int n_nodes) {
    int warp  = (blockIdx.x * blockDim.x + threadIdx.x) >> 5;
    int lane  = threadIdx.x & 31;
    int ebase = warp * EPW;
    if (ebase >= n_edges) return;

    uint64_t pol_last;
    asm("createpolicy.fractional.L2::evict_last.b64 %0, 1.0;" : "=l"(pol_last));

    const uint2*  __restrict__ node16 = reinterpret_cast<const uint2*>(g_node16);
    const float4* __restrict__ rel4   = reinterpret_cast<const float4*>(rel_emb);
    int nmax = min(n_nodes, MAX_NODES) - 1;

    // Index loads (warp-uniform broadcast).
    int s[EPW], d[EPW];
    #pragma unroll
    for (int i = 0; i < EPW; i++) {
        int e = ebase + i;
        if (e >= n_edges) e = n_edges - 1;     // 600000 % 4 == 0 anyway
        s[i] = min(max(src[e], 0), nmax);
        d[i] = min(max(dst[e], 0), nmax);
    }

    // Front-batched loads. Lane l owns dims [4l, 4l+4):
    //   node rows: uint2 = 4 halves (8B, evict_last) -> 256B/warp
    //   rel row:   float4 (16B, streaming __ldcs)    -> 512B/warp
    uint2  hq[EPW], tq[EPW];
    float4 rv[EPW];
    #pragma unroll
    for (int i = 0; i < EPW; i++) {
        asm volatile("ld.global.L2::cache_hint.v2.u32 {%0,%1}, [%2], %3;"
                     : "=r"(hq[i].x), "=r"(hq[i].y)
                     : "l"(node16 + (unsigned)s[i] * DIM4 + lane), "l"(pol_last));
        asm volatile("ld.global.L2::cache_hint.v2.u32 {%0,%1}, [%2], %3;"
                     : "=r"(tq[i].x), "=r"(tq[i].y)
                     : "l"(node16 + (unsigned)d[i] * DIM4 + lane), "l"(pol_last));
        rv[i] = __ldcs(rel4 + (unsigned)(ebase + i) * DIM4 + lane);
    }

    float acc[EPW];
    #pragma unroll
    for (int i = 0; i < EPW; i++) {
        __half2 h01 = *reinterpret_cast<__half2*>(&hq[i].x);
        __half2 h23 = *reinterpret_cast<__half2*>(&hq[i].y);
        __half2 t01 = *reinterpret_cast<__half2*>(&tq[i].x);
        __half2 t23 = *reinterpret_cast<__half2*>(&tq[i].y);
        float2 hA = __half22float2(h01), hB = __half22float2(h23);
        float2 tA = __half22float2(t01), tB = __half22float2(t23);
        acc[i] = hA.x * rv[i].x * tA.x
               + hA.y * rv[i].y * tA.y
               + hB.x * rv[i].z * tB.x
               + hB.y * rv[i].w * tB.y;
    }

    #pragma unroll
    for (int off = 16; off > 0; off >>= 1) {
        #pragma unroll
        for (int i = 0; i < EPW; i++)
            acc[i] += __shfl_xor_sync(0xffffffffu, acc[i], off);
    }

    if (lane < EPW) {
        int e = ebase + lane;
        if (e < n_edges) {
            float v = (lane == 0) ? acc[0] : (lane == 1) ? acc[1]
                    : (lane == 2) ? acc[2] : acc[3];
            out[e] = v;
        }
    }
}

extern "C" void kernel_launch(void* const* d_in, const int* in_sizes, int n_in,
                              void* d_out, int out_size) {
    const float* node_emb = (const float*)d_in[0];
    const float* rel_emb  = (const float*)d_in[1];
    const int*   src      = (const int*)d_in[2];
    const int*   dst      = (const int*)d_in[3];
    float* out = (float*)d_out;

    int n_edges = in_sizes[1] / DIM;
    int n_nodes = in_sizes[0] / DIM;
    int n_conv  = min(n_nodes, MAX_NODES);

    int total4 = n_conv * DIM4;                       // 16B groups to convert
    convert_kernel<<<(total4 + 255) / 256, 256>>>(node_emb, total4);

    int threads = 256;
    int edges_per_block = (threads / 32) * EPW;       // 32
    int blocks = (n_edges + edges_per_block - 1) / edges_per_block;
    distmult_kernel<<<blocks, threads>>>(rel_emb, src, dst, out,
                                         n_edges, n_nodes);
}

// round 12
// speedup vs baseline: 1.0051x; 1.0051x over previous
#include <cuda_runtime.h>
#include <cuda_fp16.h>

// DistMult edge score: out[e] = sum_d node[src[e]][d] * rel[e][d] * node[dst[e]][d]
// N_NODES=100000, N_EDGES=600000, DIM=128, int32 indices.
//
// Model (R10/R11 confirmed): scorer sits exactly at the LTS (L2 bandwidth)
// chip cap (~630MB L2 bytes / 55.5us = 11.3TB/s). fp16 node scratch is the
// right precision point (rel_err 2.9e-4; bf16/fp8 would breach 1e-3).
// R12: revert R11's createpolicy (cost, no benefit); leaner convert kernel
// (32B read / 16B store per thread, __ldcs read-once). Scorer = exact R10.

#define DIM       128
#define DIM4      32            // 16B groups per row
#define EPW       4             // edges per warp
#define MAX_NODES 100000

__device__ __half g_node16[(size_t)MAX_NODES * DIM];   // 25.6 MB scratch

// ---- Kernel 1: fp32 node table -> fp16 scratch (32B in / 16B out per thread) ----
__global__ __launch_bounds__(256)
void convert_kernel(const float* __restrict__ node_emb, int total8) {
    int i = blockIdx.x * blockDim.x + threadIdx.x;   // one 32-byte group
    if (i >= total8) return;

    const float4* in = reinterpret_cast<const float4*>(node_emb) + 2 * i;
    float4 v0 = __ldcs(in);          // read-once: evict-first
    float4 v1 = __ldcs(in + 1);

    __half2 a = __floats2half2_rn(v0.x, v0.y);
    __half2 b = __floats2half2_rn(v0.z, v0.w);
    __half2 c = __floats2half2_rn(v1.x, v1.y);
    __half2 d = __floats2half2_rn(v1.z, v1.w);

    uint4 o;
    o.x = *reinterpret_cast<unsigned int*>(&a);
    o.y = *reinterpret_cast<unsigned int*>(&b);
    o.z = *reinterpret_cast<unsigned int*>(&c);
    o.w = *reinterpret_cast<unsigned int*>(&d);
    reinterpret_cast<uint4*>(g_node16)[i] = o;
}

// ---- Kernel 2: scorer (exact R10 shape: measured best, at LTS cap) ----
__global__ __launch_bounds__(256)
void distmult_kernel(const float* __restrict__ rel_emb,
                     const int* __restrict__ src,
                     const int* __restrict__ dst,
                     float* __restrict__ out,
                     int n_edges,
                     int n_nodes) {
    int warp  = (blockIdx.x * blockDim.x + threadIdx.x) >> 5;
    int lane  = threadIdx.x & 31;
    int ebase = warp * EPW;
    if (ebase >= n_edges) return;

    const uint2*  __restrict__ node16 = reinterpret_cast<const uint2*>(g_node16);
    const float4* __restrict__ rel4   = reinterpret_cast<const float4*>(rel_emb);
    int nmax = min(n_nodes, MAX_NODES) - 1;

    // Index loads (warp-uniform broadcast).
    int s[EPW], d[EPW];
    #pragma unroll
    for (int i = 0; i < EPW; i++) {
        int e = ebase + i;
        if (e >= n_edges) e = n_edges - 1;     // 600000 % 4 == 0 anyway
        s[i] = min(max(src[e], 0), nmax);
        d[i] = min(max(dst[e], 0), nmax);
    }

    // Front-batched loads. Lane l owns dims [4l, 4l+4):
    //   node rows: uint2 = 4 halves (8B) -> 256B/warp
    //   rel row:   float4 (16B, streaming __ldcs) -> 512B/warp
    uint2  hq[EPW], tq[EPW];
    float4 rv[EPW];
    #pragma unroll
    for (int i = 0; i < EPW; i++) {
        hq[i] = node16[(unsigned)s[i] * DIM4 + lane];
        tq[i] = node16[(unsigned)d[i] * DIM4 + lane];
        rv[i] = __ldcs(rel4 + (unsigned)(ebase + i) * DIM4 + lane);
    }

    float acc[EPW];
    #pragma unroll
    for (int i = 0; i < EPW; i++) {
        __half2 h01 = *reinterpret_cast<__half2*>(&hq[i].x);
        __half2 h23 = *reinterpret_cast<__half2*>(&hq[i].y);
        __half2 t01 = *reinterpret_cast<__half2*>(&tq[i].x);
        __half2 t23 = *reinterpret_cast<__half2*>(&tq[i].y);
        float2 hA = __half22float2(h01), hB = __half22float2(h23);
        float2 tA = __half22float2(t01), tB = __half22float2(t23);
        acc[i] = hA.x * rv[i].x * tA.x
               + hA.y * rv[i].y * tA.y
               + hB.x * rv[i].z * tB.x
               + hB.y * rv[i].w * tB.y;
    }

    #pragma unroll
    for (int off = 16; off > 0; off >>= 1) {
        #pragma unroll
        for (int i = 0; i < EPW; i++)
            acc[i] += __shfl_xor_sync(0xffffffffu, acc[i], off);
    }

    if (lane < EPW) {
        int e = ebase + lane;
        if (e < n_edges) {
            float v = (lane == 0) ? acc[0] : (lane == 1) ? acc[1]
                    : (lane == 2) ? acc[2] : acc[3];
            out[e] = v;
        }
    }
}

extern "C" void kernel_launch(void* const* d_in, const int* in_sizes, int n_in,
                              void* d_out, int out_size) {
    const float* node_emb = (const float*)d_in[0];
    const float* rel_emb  = (const float*)d_in[1];
    const int*   src      = (const int*)d_in[2];
    const int*   dst      = (const int*)d_in[3];
    float* out = (float*)d_out;

    int n_edges = in_sizes[1] / DIM;
    int n_nodes = in_sizes[0] / DIM;
    int n_conv  = min(n_nodes, MAX_NODES);

    int total8 = n_conv * (DIM / 8);                  // 32B groups (DIM%8==0)
    convert_kernel<<<(total8 + 255) / 256, 256>>>(node_emb, total8);

    int threads = 256;
    int edges_per_block = (threads / 32) * EPW;       // 32
    int blocks = (n_edges + edges_per_block - 1) / edges_per_block;
    distmult_kernel<<<blocks, threads>>>(rel_emb, src, dst, out,
                                         n_edges, n_nodes);
}

// round 13
// speedup vs baseline: 1.0301x; 1.0249x over previous
#include <cuda_runtime.h>
#include <cuda_fp16.h>

// DistMult edge score: out[e] = sum_d node[src[e]][d] * rel[e][d] * node[dst[e]][d]
// N_NODES=100000, N_EDGES=600000, DIM=128, int32 indices.
//
// FINAL (= R10, the measured best at 61.9us):
//   Closed model: scorer is pinned at the LTS (L2-bandwidth) chip cap:
//   ~620MB L2 bytes (rel 307MB fp32 stream + 307MB fp16 node gathers) at
//   ~11.3TB/s -> 55.5us measured; + fp32->fp16 table conversion (77MB,
//   ~6.4us) -> ~62us total. R11 (L2 createpolicy) and R12 (wider convert
//   threads) both regressed the convert stage and were reverted.
//   fp16 node scratch is the right precision point: rel_err 2.94e-4 vs
//   threshold 1e-3 (bf16 ~1.2e-3 would breach; fp8 far worse).
//
// Scorer: warp per 4 edges; lane l owns dims [4l,4l+4). Node rows read as
// uint2 (4 halves, 256B/warp); rel rows as float4 via __ldcs (512B/warp,
// evict-first keeps the fp16 table + working set L2-resident).

#define DIM       128
#define DIM4      32            // 16B groups per fp32 row / uint2 groups per fp16 row
#define EPW       4             // edges per warp
#define MAX_NODES 100000

__device__ __half g_node16[(size_t)MAX_NODES * DIM];   // 25.6 MB scratch

// ---- Kernel 1: fp32 node table -> fp16 scratch (16B read / 8B write per thread) ----
__global__ __launch_bounds__(256)
void convert_kernel(const float* __restrict__ node_emb, int total4) {
    int i = blockIdx.x * blockDim.x + threadIdx.x;
    if (i >= total4) return;
    float4 v = reinterpret_cast<const float4*>(node_emb)[i];
    __half2 a = __floats2half2_rn(v.x, v.y);
    __half2 b = __floats2half2_rn(v.z, v.w);
    uint2 o;
    o.x = *reinterpret_cast<unsigned int*>(&a);
    o.y = *reinterpret_cast<unsigned int*>(&b);
    reinterpret_cast<uint2*>(g_node16)[i] = o;
}

// ---- Kernel 2: scorer (at the LTS floor for this algorithm) ----
__global__ __launch_bounds__(256)
void distmult_kernel(const float* __restrict__ rel_emb,
                     const int* __restrict__ src,
                     const int* __restrict__ dst,
                     float* __restrict__ out,
                     int n_edges,
                     int n_nodes) {
    int warp  = (blockIdx.x * blockDim.x + threadIdx.x) >> 5;
    int lane  = threadIdx.x & 31;
    int ebase = warp * EPW;
    if (ebase >= n_edges) return;

    const uint2*  __restrict__ node16 = reinterpret_cast<const uint2*>(g_node16);
    const float4* __restrict__ rel4   = reinterpret_cast<const float4*>(rel_emb);
    int nmax = min(n_nodes, MAX_NODES) - 1;

    // Index loads (warp-uniform broadcast).
    int s[EPW], d[EPW];
    #pragma unroll
    for (int i = 0; i < EPW; i++) {
        int e = ebase + i;
        if (e >= n_edges) e = n_edges - 1;     // 600000 % 4 == 0 anyway
        s[i] = min(max(src[e], 0), nmax);
        d[i] = min(max(dst[e], 0), nmax);
    }

    // Front-batched loads. Lane l owns dims [4l, 4l+4):
    //   node rows: uint2 = 4 halves (8B) -> 256B/warp
    //   rel row:   float4 (16B, streaming __ldcs) -> 512B/warp
    uint2  hq[EPW], tq[EPW];
    float4 rv[EPW];
    #pragma unroll
    for (int i = 0; i < EPW; i++) {
        hq[i] = node16[(unsigned)s[i] * DIM4 + lane];
        tq[i] = node16[(unsigned)d[i] * DIM4 + lane];
        rv[i] = __ldcs(rel4 + (unsigned)(ebase + i) * DIM4 + lane);
    }

    float acc[EPW];
    #pragma unroll
    for (int i = 0; i < EPW; i++) {
        __half2 h01 = *reinterpret_cast<__half2*>(&hq[i].x);
        __half2 h23 = *reinterpret_cast<__half2*>(&hq[i].y);
        __half2 t01 = *reinterpret_cast<__half2*>(&tq[i].x);
        __half2 t23 = *reinterpret_cast<__half2*>(&tq[i].y);
        float2 hA = __half22float2(h01), hB = __half22float2(h23);
        float2 tA = __half22float2(t01), tB = __half22float2(t23);
        acc[i] = hA.x * rv[i].x * tA.x
               + hA.y * rv[i].y * tA.y
               + hB.x * rv[i].z * tB.x
               + hB.y * rv[i].w * tB.y;
    }

    #pragma unroll
    for (int off = 16; off > 0; off >>= 1) {
        #pragma unroll
        for (int i = 0; i < EPW; i++)
            acc[i] += __shfl_xor_sync(0xffffffffu, acc[i], off);
    }

    if (lane < EPW) {
        int e = ebase + lane;
        if (e < n_edges) {
            float v = (lane == 0) ? acc[0] : (lane == 1) ? acc[1]
                    : (lane == 2) ? acc[2] : acc[3];
            out[e] = v;
        }
    }
}

extern "C" void kernel_launch(void* const* d_in, const int* in_sizes, int n_in,
                              void* d_out, int out_size) {
    const float* node_emb = (const float*)d_in[0];
    const float* rel_emb  = (const float*)d_in[1];
    const int*   src      = (const int*)d_in[2];
    const int*   dst      = (const int*)d_in[3];
    float* out = (float*)d_out;

    int n_edges = in_sizes[1] / DIM;
    int n_nodes = in_sizes[0] / DIM;
    int n_conv  = min(n_nodes, MAX_NODES);

    int total4 = n_conv * DIM4;                       // 16B groups to convert
    convert_kernel<<<(total4 + 255) / 256, 256>>>(node_emb, total4);

    int threads = 256;
    int edges_per_block = (threads / 32) * EPW;       // 32
    int blocks = (n_edges + edges_per_block - 1) / edges_per_block;
    distmult_kernel<<<blocks, threads>>>(rel_emb, src, dst, out,
                                         n_edges, n_nodes);
}